// round 3
// baseline (speedup 1.0000x reference)
#include <cuda_runtime.h>
#include <cuda_bf16.h>
#include <math.h>

// Problem constants
#define BB 8
#define SS 512
#define DD 768
#define HH 12
#define LL 12
#define DH 64
#define DF 3072
#define VV 40478
#define MTOK (BB*SS)       // 4096 tokens

// ---------------- scratch (static device allocations; no cudaMalloc) ----------
__device__ float g_h[MTOK * DD];        // residual stream
__device__ float g_qkv[MTOK * 3 * DD];  // qkv
__device__ float g_attn[MTOK * DD];     // attention context (merged heads)
__device__ float g_tmp[MTOK * DD];      // proj outputs
__device__ float g_mid[MTOK * DF];      // mlp intermediate

// ---------------- helpers ----------------
__device__ __forceinline__ float gelu_f(float x) {
    const float c = 0.7978845608028654f; // sqrt(2/pi)
    float x3 = x * x * x;
    return 0.5f * x * (1.0f + tanhf(c * (x + 0.044715f * x3)));
}

// ---------------- embedding ----------------
__global__ void embed_kernel(const int* __restrict__ tokens,
                             const float* __restrict__ we,
                             float* __restrict__ h)
{
    int t = blockIdx.x;            // 0..4095
    int s = t % SS;
    int tok = tokens[t];
    const float* wrow = we + (size_t)tok * DD;
    const float* prow = we + (size_t)(VV + s) * DD;
    float* hrow = h + (size_t)t * DD;
    for (int i = threadIdx.x; i < DD; i += blockDim.x)
        hrow[i] = wrow[i] + prow[i];
}

// ---------------- SGEMM: C[M,N] = A[M,K] @ B[K,N] + bias, opt GELU ------------
// BM=128, BN=128, BK=8, 256 threads, 8x8 per-thread tile. All dims multiples.
template<int ACT>
__global__ __launch_bounds__(256)
void sgemm_bias(const float* __restrict__ A, const float* __restrict__ B,
                const float* __restrict__ bias, float* __restrict__ C,
                int M, int N, int K)
{
    __shared__ float As[8][128];
    __shared__ float Bs[8][128];

    const int tid = threadIdx.x;
    const int tx = tid & 15;       // 0..15 -> N direction
    const int ty = tid >> 4;       // 0..15 -> M direction
    const int row0 = blockIdx.y * 128;
    const int col0 = blockIdx.x * 128;

    const int arow = tid >> 1;          // 0..127
    const int acol = (tid & 1) * 4;     // 0 or 4
    const int brow = tid >> 5;          // 0..7
    const int bcol = (tid & 31) * 4;    // 0..124

    const float* Aptr = A + (size_t)(row0 + arow) * K + acol;
    const float* Bptr = B + (size_t)brow * N + col0 + bcol;

    float acc[8][8];
    #pragma unroll
    for (int i = 0; i < 8; i++)
        #pragma unroll
        for (int j = 0; j < 8; j++) acc[i][j] = 0.0f;

    for (int kk = 0; kk < K; kk += 8) {
        float4 av = *(const float4*)(Aptr + kk);
        float4 bv = *(const float4*)(Bptr + (size_t)kk * N);
        As[acol + 0][arow] = av.x;
        As[acol + 1][arow] = av.y;
        As[acol + 2][arow] = av.z;
        As[acol + 3][arow] = av.w;
        *(float4*)&Bs[brow][bcol] = bv;
        __syncthreads();

        #pragma unroll
        for (int k = 0; k < 8; k++) {
            float a[8], b[8];
            #pragma unroll
            for (int i = 0; i < 8; i++) a[i] = As[k][ty * 8 + i];
            #pragma unroll
            for (int j = 0; j < 8; j++) b[j] = Bs[k][tx * 8 + j];
            #pragma unroll
            for (int i = 0; i < 8; i++)
                #pragma unroll
                for (int j = 0; j < 8; j++)
                    acc[i][j] = fmaf(a[i], b[j], acc[i][j]);
        }
        __syncthreads();
    }

    // epilogue: bias (+ gelu), vectorized stores
    float bv0[8];
    #pragma unroll
    for (int j = 0; j < 8; j++) bv0[j] = bias[col0 + tx * 8 + j];

    #pragma unroll
    for (int i = 0; i < 8; i++) {
        int r = row0 + ty * 8 + i;
        float* Crow = C + (size_t)r * N + col0 + tx * 8;
        float vout[8];
        #pragma unroll
        for (int j = 0; j < 8; j++) {
            float v = acc[i][j] + bv0[j];
            if (ACT == 1) v = gelu_f(v);
            vout[j] = v;
        }
        *(float4*)(Crow + 0) = make_float4(vout[0], vout[1], vout[2], vout[3]);
        *(float4*)(Crow + 4) = make_float4(vout[4], vout[5], vout[6], vout[7]);
    }
}

// ---------------- causal attention, one block per (query pos, head, batch) ----
__global__ __launch_bounds__(128)
void attn_kernel(const float* __restrict__ qkv, float* __restrict__ out)
{
    const int si = blockIdx.x;   // query position
    const int hh = blockIdx.y;   // head
    const int b  = blockIdx.z;   // batch
    const int tid = threadIdx.x;

    const float* base = qkv + (size_t)(b * SS) * (3 * DD);
    const float* qrow = base + (size_t)si * (3 * DD) + hh * DH;

    __shared__ float qs[DH];
    __shared__ float sc[SS];
    __shared__ float red[128];

    if (tid < DH) qs[tid] = qrow[tid] * 0.125f;   // 1/sqrt(64)
    __syncthreads();

    const int nk = si + 1;  // causal
    for (int j = tid; j < nk; j += 128) {
        const float* krow = base + (size_t)j * (3 * DD) + DD + hh * DH;
        float s = 0.0f;
        #pragma unroll
        for (int d = 0; d < DH; d++) s = fmaf(qs[d], krow[d], s);
        sc[j] = s;
    }
    __syncthreads();

    // row max
    float m = -1e30f;
    for (int j = tid; j < nk; j += 128) m = fmaxf(m, sc[j]);
    red[tid] = m; __syncthreads();
    for (int st = 64; st > 0; st >>= 1) {
        if (tid < st) red[tid] = fmaxf(red[tid], red[tid + st]);
        __syncthreads();
    }
    m = red[0];
    __syncthreads();

    // exp + sum
    float lsum = 0.0f;
    for (int j = tid; j < nk; j += 128) {
        float e = expf(sc[j] - m);
        sc[j] = e;
        lsum += e;
    }
    red[tid] = lsum; __syncthreads();
    for (int st = 64; st > 0; st >>= 1) {
        if (tid < st) red[tid] += red[tid + st];
        __syncthreads();
    }
    const float inv = 1.0f / red[0];

    // weighted sum over V (threads 0..63 own one output dim each)
    if (tid < DH) {
        float acc = 0.0f;
        const float* vbase = base + 2 * DD + hh * DH + tid;
        for (int j = 0; j < nk; j++)
            acc = fmaf(sc[j], vbase[(size_t)j * (3 * DD)], acc);
        out[(size_t)(b * SS + si) * DD + hh * DH + tid] = acc * inv;
    }
}

// ---------------- fused residual add + LayerNorm (one block per row) ----------
__global__ __launch_bounds__(256)
void add_ln_kernel(const float* __restrict__ x, const float* __restrict__ a,
                   const float* __restrict__ g, const float* __restrict__ bb,
                   float* __restrict__ out)
{
    const int row = blockIdx.x;
    const int tid = threadIdx.x;
    __shared__ float red[256];

    const size_t off = (size_t)row * DD;
    float v[3];
    float s = 0.0f;
    #pragma unroll
    for (int i = 0; i < 3; i++) {
        int c = tid + 256 * i;
        v[i] = x[off + c] + a[off + c];
        s += v[i];
    }
    red[tid] = s; __syncthreads();
    for (int st = 128; st > 0; st >>= 1) {
        if (tid < st) red[tid] += red[tid + st];
        __syncthreads();
    }
    const float mean = red[0] * (1.0f / DD);
    __syncthreads();

    float s2 = 0.0f;
    #pragma unroll
    for (int i = 0; i < 3; i++) {
        float d = v[i] - mean;
        s2 += d * d;
    }
    red[tid] = s2; __syncthreads();
    for (int st = 128; st > 0; st >>= 1) {
        if (tid < st) red[tid] += red[tid + st];
        __syncthreads();
    }
    const float inv = rsqrtf(red[0] * (1.0f / DD) + 1e-5f);

    #pragma unroll
    for (int i = 0; i < 3; i++) {
        int c = tid + 256 * i;
        out[off + c] = g[c] * (v[i] - mean) * inv + bb[c];
    }
}

// ---------------- launch ----------------
extern "C" void kernel_launch(void* const* d_in, const int* in_sizes, int n_in,
                              void* d_out, int out_size)
{
    const int*   tokens = (const int*)  d_in[0];
    const float* we     = (const float*)d_in[1];
    const float* wqkv   = (const float*)d_in[2];
    const float* bqkv   = (const float*)d_in[3];
    const float* wproj  = (const float*)d_in[4];
    const float* bproj  = (const float*)d_in[5];
    const float* g1     = (const float*)d_in[6];
    const float* b1     = (const float*)d_in[7];
    const float* wfc    = (const float*)d_in[8];
    const float* bfc    = (const float*)d_in[9];
    const float* wpr    = (const float*)d_in[10];
    const float* bpr    = (const float*)d_in[11];
    const float* g2     = (const float*)d_in[12];
    const float* b2     = (const float*)d_in[13];
    float* out = (float*)d_out;

    float *h, *qkv, *attn, *tmp, *mid;
    cudaGetSymbolAddress((void**)&h,    g_h);
    cudaGetSymbolAddress((void**)&qkv,  g_qkv);
    cudaGetSymbolAddress((void**)&attn, g_attn);
    cudaGetSymbolAddress((void**)&tmp,  g_tmp);
    cudaGetSymbolAddress((void**)&mid,  g_mid);

    embed_kernel<<<MTOK, 256>>>(tokens, we, h);

    for (int l = 0; l < LL; l++) {
        const float* wq = wqkv  + (size_t)l * DD * 3 * DD;
        const float* bq = bqkv  + (size_t)l * 3 * DD;
        const float* wp = wproj + (size_t)l * DD * DD;
        const float* bp = bproj + (size_t)l * DD;
        const float* gA = g1 + (size_t)l * DD;
        const float* bA = b1 + (size_t)l * DD;
        const float* wf = wfc + (size_t)l * DD * DF;
        const float* bf = bfc + (size_t)l * DF;
        const float* wr = wpr + (size_t)l * DF * DD;
        const float* br = bpr + (size_t)l * DD;
        const float* gB = g2 + (size_t)l * DD;
        const float* bBv = b2 + (size_t)l * DD;

        // qkv = h @ wq + bq     [4096 x 2304]
        sgemm_bias<0><<<dim3(3 * DD / 128, MTOK / 128), 256>>>(
            h, wq, bq, qkv, MTOK, 3 * DD, DD);

        // attention
        attn_kernel<<<dim3(SS, HH, BB), 128>>>(qkv, attn);

        // a = attn @ wp + bp    [4096 x 768]
        sgemm_bias<0><<<dim3(DD / 128, MTOK / 128), 256>>>(
            attn, wp, bp, tmp, MTOK, DD, DD);

        // n = LN(h + a)  (in place into h)
        add_ln_kernel<<<MTOK, 256>>>(h, tmp, gA, bA, h);

        // mid = gelu(n @ wf + bf)   [4096 x 3072]
        sgemm_bias<1><<<dim3(DF / 128, MTOK / 128), 256>>>(
            h, wf, bf, mid, MTOK, DF, DD);

        // m = mid @ wr + br    [4096 x 768]
        sgemm_bias<0><<<dim3(DD / 128, MTOK / 128), 256>>>(
            mid, wr, br, tmp, MTOK, DD, DF);

        // h = LN(n + m); last layer writes directly to output
        float* o = (l == LL - 1) ? out : h;
        add_ln_kernel<<<MTOK, 256>>>(h, tmp, gB, bBv, o);
    }
}

// round 4
// speedup vs baseline: 1.0013x; 1.0013x over previous
#include <cuda_runtime.h>
#include <cuda_bf16.h>
#include <math.h>

// Problem constants
#define BB 8
#define SS 512
#define DD 768
#define HH 12
#define LL 12
#define DH 64
#define DF 3072
#define VV 40478
#define MTOK (BB*SS)       // 4096 tokens

// ---------------- scratch (static device allocations; no cudaMalloc) ----------
__device__ float g_h[MTOK * DD];        // residual stream
__device__ float g_qkv[MTOK * 3 * DD];  // qkv
__device__ float g_attn[MTOK * DD];     // attention context (merged heads)
__device__ float g_tmp[MTOK * DD];      // proj outputs
__device__ float g_mid[MTOK * DF];      // mlp intermediate

// ---------------- helpers ----------------
__device__ __forceinline__ float gelu_f(float x) {
    const float c = 0.7978845608028654f; // sqrt(2/pi)
    float x3 = x * x * x;
    return 0.5f * x * (1.0f + tanhf(c * (x + 0.044715f * x3)));
}

// ---------------- embedding ----------------
__global__ void embed_kernel(const int* __restrict__ tokens,
                             const float* __restrict__ we,
                             float* __restrict__ h)
{
    int t = blockIdx.x;            // 0..4095
    int s = t % SS;
    int tok = tokens[t];
    const float* wrow = we + (size_t)tok * DD;
    const float* prow = we + (size_t)(VV + s) * DD;
    float* hrow = h + (size_t)t * DD;
    for (int i = threadIdx.x; i < DD; i += blockDim.x)
        hrow[i] = wrow[i] + prow[i];
}

// ---------------- SGEMM: C[M,N] = A[M,K] @ B[K,N] + bias, opt GELU ------------
// BM=128, BN=128, BK=8, 256 threads, 8x8 per-thread tile. All dims multiples.
template<int ACT>
__global__ __launch_bounds__(256)
void sgemm_bias(const float* __restrict__ A, const float* __restrict__ B,
                const float* __restrict__ bias, float* __restrict__ C,
                int M, int N, int K)
{
    __shared__ float As[8][128];
    __shared__ float Bs[8][128];

    const int tid = threadIdx.x;
    const int tx = tid & 15;       // 0..15 -> N direction
    const int ty = tid >> 4;       // 0..15 -> M direction
    const int row0 = blockIdx.y * 128;
    const int col0 = blockIdx.x * 128;

    const int arow = tid >> 1;          // 0..127
    const int acol = (tid & 1) * 4;     // 0 or 4
    const int brow = tid >> 5;          // 0..7
    const int bcol = (tid & 31) * 4;    // 0..124

    const float* Aptr = A + (size_t)(row0 + arow) * K + acol;
    const float* Bptr = B + (size_t)brow * N + col0 + bcol;

    float acc[8][8];
    #pragma unroll
    for (int i = 0; i < 8; i++)
        #pragma unroll
        for (int j = 0; j < 8; j++) acc[i][j] = 0.0f;

    for (int kk = 0; kk < K; kk += 8) {
        float4 av = *(const float4*)(Aptr + kk);
        float4 bv = *(const float4*)(Bptr + (size_t)kk * N);
        As[acol + 0][arow] = av.x;
        As[acol + 1][arow] = av.y;
        As[acol + 2][arow] = av.z;
        As[acol + 3][arow] = av.w;
        *(float4*)&Bs[brow][bcol] = bv;
        __syncthreads();

        #pragma unroll
        for (int k = 0; k < 8; k++) {
            float a[8], b[8];
            #pragma unroll
            for (int i = 0; i < 8; i++) a[i] = As[k][ty * 8 + i];
            #pragma unroll
            for (int j = 0; j < 8; j++) b[j] = Bs[k][tx * 8 + j];
            #pragma unroll
            for (int i = 0; i < 8; i++)
                #pragma unroll
                for (int j = 0; j < 8; j++)
                    acc[i][j] = fmaf(a[i], b[j], acc[i][j]);
        }
        __syncthreads();
    }

    // epilogue: bias (+ gelu), vectorized stores
    float bv0[8];
    #pragma unroll
    for (int j = 0; j < 8; j++) bv0[j] = bias[col0 + tx * 8 + j];

    #pragma unroll
    for (int i = 0; i < 8; i++) {
        int r = row0 + ty * 8 + i;
        float* Crow = C + (size_t)r * N + col0 + tx * 8;
        float vout[8];
        #pragma unroll
        for (int j = 0; j < 8; j++) {
            float v = acc[i][j] + bv0[j];
            if (ACT == 1) v = gelu_f(v);
            vout[j] = v;
        }
        *(float4*)(Crow + 0) = make_float4(vout[0], vout[1], vout[2], vout[3]);
        *(float4*)(Crow + 4) = make_float4(vout[4], vout[5], vout[6], vout[7]);
    }
}

// ---------------- causal attention, one block per (query pos, head, batch) ----
__global__ __launch_bounds__(128)
void attn_kernel(const float* __restrict__ qkv, float* __restrict__ out)
{
    const int si = blockIdx.x;   // query position
    const int hh = blockIdx.y;   // head
    const int b  = blockIdx.z;   // batch
    const int tid = threadIdx.x;

    const float* base = qkv + (size_t)(b * SS) * (3 * DD);
    const float* qrow = base + (size_t)si * (3 * DD) + hh * DH;

    __shared__ float qs[DH];
    __shared__ float sc[SS];
    __shared__ float red[128];

    if (tid < DH) qs[tid] = qrow[tid] * 0.125f;   // 1/sqrt(64)
    __syncthreads();

    const int nk = si + 1;  // causal
    for (int j = tid; j < nk; j += 128) {
        const float* krow = base + (size_t)j * (3 * DD) + DD + hh * DH;
        float s = 0.0f;
        #pragma unroll
        for (int d = 0; d < DH; d++) s = fmaf(qs[d], krow[d], s);
        sc[j] = s;
    }
    __syncthreads();

    // row max
    float m = -1e30f;
    for (int j = tid; j < nk; j += 128) m = fmaxf(m, sc[j]);
    red[tid] = m; __syncthreads();
    for (int st = 64; st > 0; st >>= 1) {
        if (tid < st) red[tid] = fmaxf(red[tid], red[tid + st]);
        __syncthreads();
    }
    m = red[0];
    __syncthreads();

    // exp + sum
    float lsum = 0.0f;
    for (int j = tid; j < nk; j += 128) {
        float e = expf(sc[j] - m);
        sc[j] = e;
        lsum += e;
    }
    red[tid] = lsum; __syncthreads();
    for (int st = 64; st > 0; st >>= 1) {
        if (tid < st) red[tid] += red[tid + st];
        __syncthreads();
    }
    const float inv = 1.0f / red[0];

    // weighted sum over V (threads 0..63 own one output dim each)
    if (tid < DH) {
        float acc = 0.0f;
        const float* vbase = base + 2 * DD + hh * DH + tid;
        for (int j = 0; j < nk; j++)
            acc = fmaf(sc[j], vbase[(size_t)j * (3 * DD)], acc);
        out[(size_t)(b * SS + si) * DD + hh * DH + tid] = acc * inv;
    }
}

// ---------------- fused residual add + LayerNorm (one block per row) ----------
__global__ __launch_bounds__(256)
void add_ln_kernel(const float* __restrict__ x, const float* __restrict__ a,
                   const float* __restrict__ g, const float* __restrict__ bb,
                   float* __restrict__ out)
{
    const int row = blockIdx.x;
    const int tid = threadIdx.x;
    __shared__ float red[256];

    const size_t off = (size_t)row * DD;
    float v[3];
    float s = 0.0f;
    #pragma unroll
    for (int i = 0; i < 3; i++) {
        int c = tid + 256 * i;
        v[i] = x[off + c] + a[off + c];
        s += v[i];
    }
    red[tid] = s; __syncthreads();
    for (int st = 128; st > 0; st >>= 1) {
        if (tid < st) red[tid] += red[tid + st];
        __syncthreads();
    }
    const float mean = red[0] * (1.0f / DD);
    __syncthreads();

    float s2 = 0.0f;
    #pragma unroll
    for (int i = 0; i < 3; i++) {
        float d = v[i] - mean;
        s2 += d * d;
    }
    red[tid] = s2; __syncthreads();
    for (int st = 128; st > 0; st >>= 1) {
        if (tid < st) red[tid] += red[tid + st];
        __syncthreads();
    }
    const float inv = rsqrtf(red[0] * (1.0f / DD) + 1e-5f);

    #pragma unroll
    for (int i = 0; i < 3; i++) {
        int c = tid + 256 * i;
        out[off + c] = g[c] * (v[i] - mean) * inv + bb[c];
    }
}

// ---------------- launch ----------------
extern "C" void kernel_launch(void* const* d_in, const int* in_sizes, int n_in,
                              void* d_out, int out_size)
{
    const int*   tokens = (const int*)  d_in[0];
    const float* we     = (const float*)d_in[1];
    const float* wqkv   = (const float*)d_in[2];
    const float* bqkv   = (const float*)d_in[3];
    const float* wproj  = (const float*)d_in[4];
    const float* bproj  = (const float*)d_in[5];
    const float* g1     = (const float*)d_in[6];
    const float* b1     = (const float*)d_in[7];
    const float* wfc    = (const float*)d_in[8];
    const float* bfc    = (const float*)d_in[9];
    const float* wpr    = (const float*)d_in[10];
    const float* bpr    = (const float*)d_in[11];
    const float* g2     = (const float*)d_in[12];
    const float* b2     = (const float*)d_in[13];
    float* out = (float*)d_out;

    float *h, *qkv, *attn, *tmp, *mid;
    cudaGetSymbolAddress((void**)&h,    g_h);
    cudaGetSymbolAddress((void**)&qkv,  g_qkv);
    cudaGetSymbolAddress((void**)&attn, g_attn);
    cudaGetSymbolAddress((void**)&tmp,  g_tmp);
    cudaGetSymbolAddress((void**)&mid,  g_mid);

    embed_kernel<<<MTOK, 256>>>(tokens, we, h);

    for (int l = 0; l < LL; l++) {
        const float* wq = wqkv  + (size_t)l * DD * 3 * DD;
        const float* bq = bqkv  + (size_t)l * 3 * DD;
        const float* wp = wproj + (size_t)l * DD * DD;
        const float* bp = bproj + (size_t)l * DD;
        const float* gA = g1 + (size_t)l * DD;
        const float* bA = b1 + (size_t)l * DD;
        const float* wf = wfc + (size_t)l * DD * DF;
        const float* bf = bfc + (size_t)l * DF;
        const float* wr = wpr + (size_t)l * DF * DD;
        const float* br = bpr + (size_t)l * DD;
        const float* gB = g2 + (size_t)l * DD;
        const float* bBv = b2 + (size_t)l * DD;

        // qkv = h @ wq + bq     [4096 x 2304]
        sgemm_bias<0><<<dim3(3 * DD / 128, MTOK / 128), 256>>>(
            h, wq, bq, qkv, MTOK, 3 * DD, DD);

        // attention
        attn_kernel<<<dim3(SS, HH, BB), 128>>>(qkv, attn);

        // a = attn @ wp + bp    [4096 x 768]
        sgemm_bias<0><<<dim3(DD / 128, MTOK / 128), 256>>>(
            attn, wp, bp, tmp, MTOK, DD, DD);

        // n = LN(h + a)  (in place into h)
        add_ln_kernel<<<MTOK, 256>>>(h, tmp, gA, bA, h);

        // mid = gelu(n @ wf + bf)   [4096 x 3072]
        sgemm_bias<1><<<dim3(DF / 128, MTOK / 128), 256>>>(
            h, wf, bf, mid, MTOK, DF, DD);

        // m = mid @ wr + br    [4096 x 768]
        sgemm_bias<0><<<dim3(DD / 128, MTOK / 128), 256>>>(
            mid, wr, br, tmp, MTOK, DD, DF);

        // h = LN(n + m); last layer writes directly to output
        float* o = (l == LL - 1) ? out : h;
        add_ln_kernel<<<MTOK, 256>>>(h, tmp, gB, bBv, o);
    }
}

// round 6
// speedup vs baseline: 3.8295x; 3.8246x over previous
#include <cuda_runtime.h>
#include <cuda_bf16.h>
#include <math.h>
#include <stdint.h>

#define BB 8
#define SS 512
#define DD 768
#define HH 12
#define LL 12
#define DH 64
#define DF 3072
#define VV 40478
#define MTOK (BB*SS)

#define K3_D  (3*DD)       // 2304
#define K3_F  (3*DF)       // 9216

#define WQ_ELEMS ((size_t)(3*DD) * K3_D)
#define WP_ELEMS ((size_t)DD * K3_D)
#define WF_ELEMS ((size_t)DF * K3_D)
#define WR_ELEMS ((size_t)DD * K3_F)
#define WL_ELEMS (WQ_ELEMS + WP_ELEMS + WF_ELEMS + WR_ELEMS)
#define OFF_Q 0
#define OFF_P (WQ_ELEMS)
#define OFF_F (WQ_ELEMS + WP_ELEMS)
#define OFF_R (WQ_ELEMS + WP_ELEMS + WF_ELEMS)

// ---------------- static scratch ----------------
__device__ __align__(1024) float g_h[MTOK * DD];
__device__ __align__(1024) float g_qkv[MTOK * 3 * DD];
__device__ __align__(1024) float g_attn[MTOK * DD];
__device__ __align__(1024) float g_tmp[MTOK * DD];
__device__ __align__(1024) float g_mid[MTOK * DF];
__device__ __align__(1024) __nv_bfloat16 g_wexp[12 * WL_ELEMS];
__device__ __align__(1024) __nv_bfloat16 g_xe[(size_t)MTOK * K3_F];

// ---------------- PTX helpers (generic sm_80+ only) ----------------
__device__ __forceinline__ uint32_t smem_u32(const void* p) {
    uint32_t a;
    asm("{ .reg .u64 t; cvta.to.shared.u64 t, %1; cvt.u32.u64 %0, t; }"
        : "=r"(a) : "l"(p));
    return a;
}
__device__ __forceinline__ void cp16(uint32_t dst, const void* src) {
    asm volatile("cp.async.cg.shared.global [%0], [%1], 16;" :: "r"(dst), "l"(src));
}
__device__ __forceinline__ void cp_commit() {
    asm volatile("cp.async.commit_group;" ::);
}
template<int N>
__device__ __forceinline__ void cp_wait() {
    asm volatile("cp.async.wait_group %0;" :: "n"(N));
}
__device__ __forceinline__ void mma16816(float* c, const uint32_t* a, const uint32_t* b) {
    asm volatile(
        "mma.sync.aligned.m16n8k16.row.col.f32.bf16.bf16.f32 "
        "{%0,%1,%2,%3}, {%4,%5,%6,%7}, {%8,%9}, {%0,%1,%2,%3};"
        : "+f"(c[0]), "+f"(c[1]), "+f"(c[2]), "+f"(c[3])
        : "r"(a[0]), "r"(a[1]), "r"(a[2]), "r"(a[3]), "r"(b[0]), "r"(b[1]));
}

__device__ __forceinline__ float gelu_f(float x) {
    const float c = 0.7978845608028654f;
    float x3 = x * x * x;
    return 0.5f * x * (1.0f + tanhf(c * (x + 0.044715f * x3)));
}

// ---------------- embedding ----------------
__global__ void embed_kernel(const int* __restrict__ tokens,
                             const float* __restrict__ we,
                             float* __restrict__ h)
{
    int t = blockIdx.x;
    int s = t % SS;
    int tok = tokens[t];
    const float* wrow = we + (size_t)tok * DD;
    const float* prow = we + (size_t)(VV + s) * DD;
    float* hrow = h + (size_t)t * DD;
    for (int i = threadIdx.x; i < DD; i += blockDim.x)
        hrow[i] = wrow[i] + prow[i];
}

// --------- weight transpose + split: W[K,N] -> We[N,3K] = [hi|hi|lo] --------
__global__ __launch_bounds__(256)
void wexpand(const float* __restrict__ W, __nv_bfloat16* __restrict__ We,
             int K, int N)
{
    __shared__ float t[32][33];
    const int n0 = blockIdx.x * 32;
    const int k0 = blockIdx.y * 32;
    const int tx = threadIdx.x & 31;
    const int ty = threadIdx.x >> 5;
    for (int r = ty; r < 32; r += 8)
        t[r][tx] = W[(size_t)(k0 + r) * N + n0 + tx];
    __syncthreads();
    for (int r = ty; r < 32; r += 8) {
        int n = n0 + r, k = k0 + tx;
        float v = t[tx][r];
        __nv_bfloat16 hi = __float2bfloat16(v);
        float lo = v - __bfloat162float(hi);
        size_t ro = (size_t)n * (3 * K);
        We[ro + k]         = hi;
        We[ro + K + k]     = hi;
        We[ro + 2 * K + k] = __float2bfloat16(lo);
    }
}

// --------- activation split: X[M,K] -> Xe[M,3K] = [hi|lo|hi] ---------------
__global__ __launch_bounds__(256)
void act_expand(const float* __restrict__ X, __nv_bfloat16* __restrict__ Xe, int K)
{
    const int m = blockIdx.y;
    const int k = blockIdx.x * 256 + threadIdx.x;
    float v = X[(size_t)m * K + k];
    __nv_bfloat16 hi = __float2bfloat16(v);
    float lo = v - __bfloat162float(hi);
    size_t ro = (size_t)m * (3 * K);
    Xe[ro + k]         = hi;
    Xe[ro + K + k]     = __float2bfloat16(lo);
    Xe[ro + 2 * K + k] = hi;
}

// ---------------- mma.sync bf16 GEMM: C = A[M,K3] @ B[N,K3]^T + bias --------
// 128x128 tile, BK=32, 4-stage cp.async pipeline, 8 warps (4M x 2N),
// per-warp 32x64 via m16n8k16. Padded SMEM rows (40 elems) -> conflict-free.
#define MSTAGES 4
#define APAD 40
#define ASTG (128 * APAD)              // elems per tile (A or B) = 5120
#define STG_ELEMS (2 * ASTG)           // per stage (A+B) = 10240 elems
#define GEMM_SMEM (MSTAGES * STG_ELEMS * 2)   // bytes = 81920

__global__ __launch_bounds__(256, 2)
void gemm_mma(const __nv_bfloat16* __restrict__ A, const __nv_bfloat16* __restrict__ B,
              const float* __restrict__ bias, float* __restrict__ C,
              int N, int K3, int act)
{
    extern __shared__ __nv_bfloat16 sh[];
    const int tid  = threadIdx.x;
    const int wid  = tid >> 5;
    const int lane = tid & 31;
    const int m0 = blockIdx.y * 128;
    const int n0 = blockIdx.x * 128;
    const int wm = (wid & 3) * 32;     // warp M offset
    const int wn = (wid >> 2) * 64;    // warp N offset

    const __nv_bfloat16* Ab = A + (size_t)m0 * K3;
    const __nv_bfloat16* Bb = B + (size_t)n0 * K3;

    // two 16B chunks of A and two of B per thread per stage
    const int id0 = tid * 2, id1 = tid * 2 + 1;
    const int ra0 = id0 >> 2, ca0 = (id0 & 3) * 8;
    const int ra1 = id1 >> 2, ca1 = (id1 & 3) * 8;

    auto issue = [&](int kc, int st) {
        __nv_bfloat16* Sa = sh + st * STG_ELEMS;
        __nv_bfloat16* Sb = Sa + ASTG;
        const __nv_bfloat16* ga = Ab + (size_t)kc * 32;
        const __nv_bfloat16* gb = Bb + (size_t)kc * 32;
        cp16(smem_u32(Sa + ra0 * APAD + ca0), ga + (size_t)ra0 * K3 + ca0);
        cp16(smem_u32(Sa + ra1 * APAD + ca1), ga + (size_t)ra1 * K3 + ca1);
        cp16(smem_u32(Sb + ra0 * APAD + ca0), gb + (size_t)ra0 * K3 + ca0);
        cp16(smem_u32(Sb + ra1 * APAD + ca1), gb + (size_t)ra1 * K3 + ca1);
        cp_commit();
    };

    const int nk = K3 >> 5;
    #pragma unroll
    for (int s = 0; s < MSTAGES - 1; s++) issue(s, s);

    float acc[2][8][4];
    #pragma unroll
    for (int mt = 0; mt < 2; mt++)
        #pragma unroll
        for (int nt = 0; nt < 8; nt++)
            #pragma unroll
            for (int i = 0; i < 4; i++) acc[mt][nt][i] = 0.0f;

    for (int kc = 0; kc < nk; kc++) {
        cp_wait<MSTAGES - 2>();
        __syncthreads();
        if (kc + MSTAGES - 1 < nk) issue(kc + MSTAGES - 1, (kc + MSTAGES - 1) & 3);

        const __nv_bfloat16* Sa = sh + (kc & 3) * STG_ELEMS;
        const __nv_bfloat16* Sb = Sa + ASTG;

        #pragma unroll
        for (int ks = 0; ks < 2; ks++) {
            const int kb = ks * 16 + (lane & 3) * 2;
            uint32_t af[2][4], bfr[8][2];
            #pragma unroll
            for (int mt = 0; mt < 2; mt++) {
                const __nv_bfloat16* p = Sa + (wm + mt * 16 + (lane >> 2)) * APAD;
                af[mt][0] = *(const uint32_t*)(p + kb);
                af[mt][1] = *(const uint32_t*)(p + 8 * APAD + kb);
                af[mt][2] = *(const uint32_t*)(p + kb + 8);
                af[mt][3] = *(const uint32_t*)(p + 8 * APAD + kb + 8);
            }
            #pragma unroll
            for (int nt = 0; nt < 8; nt++) {
                const __nv_bfloat16* p = Sb + (wn + nt * 8 + (lane >> 2)) * APAD;
                bfr[nt][0] = *(const uint32_t*)(p + kb);
                bfr[nt][1] = *(const uint32_t*)(p + kb + 8);
            }
            #pragma unroll
            for (int mt = 0; mt < 2; mt++)
                #pragma unroll
                for (int nt = 0; nt < 8; nt++)
                    mma16816(acc[mt][nt], af[mt], bfr[nt]);
        }
    }

    // epilogue
    #pragma unroll
    for (int mt = 0; mt < 2; mt++) {
        const int r = m0 + wm + mt * 16 + (lane >> 2);
        #pragma unroll
        for (int nt = 0; nt < 8; nt++) {
            const int c = n0 + wn + nt * 8 + (lane & 3) * 2;
            const float b0 = bias[c], b1 = bias[c + 1];
            float v0 = acc[mt][nt][0] + b0;
            float v1 = acc[mt][nt][1] + b1;
            float v2 = acc[mt][nt][2] + b0;
            float v3 = acc[mt][nt][3] + b1;
            if (act) { v0 = gelu_f(v0); v1 = gelu_f(v1); v2 = gelu_f(v2); v3 = gelu_f(v3); }
            *(float2*)(C + (size_t)r * N + c)       = make_float2(v0, v1);
            *(float2*)(C + (size_t)(r + 8) * N + c) = make_float2(v2, v3);
        }
    }
}

// ---------------- flash attention (SIMT fp32) -----------------------------
#define ASTR_Q 132
#define ASTR_K 68
#define ATTN_FLOATS (64*ASTR_Q + 64*ASTR_K + 64*ASTR_K + 128*ASTR_K + 128 + 128 + 128*17)
#define ATTN_DSMEM (ATTN_FLOATS * 4)

__global__ __launch_bounds__(256)
void attn_flash(const float* __restrict__ qkv, float* __restrict__ out)
{
    extern __shared__ float af[];
    float* Qs   = af;                     // [64][ASTR_Q]  Qs[d][q]
    float* Ks   = Qs + 64 * ASTR_Q;       // [64][ASTR_K]  Ks[d][k]
    float* Vs   = Ks + 64 * ASTR_K;       // [64][ASTR_K]  Vs[k][d]
    float* Ps   = Vs + 64 * ASTR_K;       // [128][ASTR_K] Ps[q][k]
    float* mrow = Ps + 128 * ASTR_K;      // [128]
    float* lrow = mrow + 128;             // [128]
    float* red  = lrow + 128;             // [128][17]

    const int tid = threadIdx.x;
    const int tx = tid & 15;
    const int ty = tid >> 4;
    const int q0 = ty * 8;
    const int k0 = tx * 4;
    const int qt = blockIdx.x;
    const int h  = blockIdx.y;
    const int b  = blockIdx.z;
    const float* base = qkv + (size_t)b * SS * (3 * DD);

    for (int i = tid; i < 128 * 16; i += 256) {
        int q = i >> 4, d = (i & 15) * 4;
        float4 v = *(const float4*)(base + (size_t)(qt * 128 + q) * (3 * DD) + h * 64 + d);
        Qs[(d + 0) * ASTR_Q + q] = v.x * 0.125f;
        Qs[(d + 1) * ASTR_Q + q] = v.y * 0.125f;
        Qs[(d + 2) * ASTR_Q + q] = v.z * 0.125f;
        Qs[(d + 3) * ASTR_Q + q] = v.w * 0.125f;
    }
    if (tid < 128) { mrow[tid] = -1e30f; lrow[tid] = 0.0f; }

    float Oacc[8][4];
    #pragma unroll
    for (int i = 0; i < 8; i++)
        #pragma unroll
        for (int j = 0; j < 4; j++) Oacc[i][j] = 0.0f;

    const int nkt = (qt + 1) * 2;
    for (int kt = 0; kt < nkt; kt++) {
        __syncthreads();
        for (int i = tid; i < 64 * 16; i += 256) {
            int kk = i >> 4, d = (i & 15) * 4;
            const float* kp = base + (size_t)(kt * 64 + kk) * (3 * DD) + DD + h * 64 + d;
            float4 v = *(const float4*)kp;
            Ks[(d + 0) * ASTR_K + kk] = v.x;
            Ks[(d + 1) * ASTR_K + kk] = v.y;
            Ks[(d + 2) * ASTR_K + kk] = v.z;
            Ks[(d + 3) * ASTR_K + kk] = v.w;
            const float* vp = base + (size_t)(kt * 64 + kk) * (3 * DD) + 2 * DD + h * 64 + d;
            *(float4*)(Vs + kk * ASTR_K + d) = *(const float4*)vp;
        }
        __syncthreads();

        float s[8][4];
        #pragma unroll
        for (int i = 0; i < 8; i++)
            #pragma unroll
            for (int j = 0; j < 4; j++) s[i][j] = 0.0f;

        for (int d = 0; d < 64; d++) {
            float4 kv = *(const float4*)(Ks + d * ASTR_K + k0);
            float4 qa = *(const float4*)(Qs + d * ASTR_Q + q0);
            float4 qb = *(const float4*)(Qs + d * ASTR_Q + q0 + 4);
            float qv[8] = {qa.x, qa.y, qa.z, qa.w, qb.x, qb.y, qb.z, qb.w};
            float kk[4] = {kv.x, kv.y, kv.z, kv.w};
            #pragma unroll
            for (int i = 0; i < 8; i++)
                #pragma unroll
                for (int j = 0; j < 4; j++)
                    s[i][j] = fmaf(qv[i], kk[j], s[i][j]);
        }

        if (kt >= 2 * qt) {
            const int diag = (kt - 2 * qt) * 64;
            #pragma unroll
            for (int i = 0; i < 8; i++)
                #pragma unroll
                for (int j = 0; j < 4; j++)
                    if (q0 + i < diag + k0 + j) s[i][j] = -1e9f;
        }

        #pragma unroll
        for (int i = 0; i < 8; i++) {
            float m4 = fmaxf(fmaxf(s[i][0], s[i][1]), fmaxf(s[i][2], s[i][3]));
            red[(q0 + i) * 17 + tx] = m4;
        }
        __syncthreads();
        if (tid < 128) {
            float m = mrow[tid];
            float mn = m;
            #pragma unroll
            for (int t = 0; t < 16; t++) mn = fmaxf(mn, red[tid * 17 + t]);
            red[tid * 17 + 16] = __expf(m - mn);
            mrow[tid] = mn;
        }
        __syncthreads();

        #pragma unroll
        for (int i = 0; i < 8; i++) {
            float m = mrow[q0 + i];
            float ps = 0.0f;
            #pragma unroll
            for (int j = 0; j < 4; j++) {
                float p = __expf(s[i][j] - m);
                Ps[(q0 + i) * ASTR_K + k0 + j] = p;
                ps += p;
            }
            red[(q0 + i) * 17 + tx] = ps;
        }
        __syncthreads();
        if (tid < 128) {
            float ssum = 0.0f;
            #pragma unroll
            for (int t = 0; t < 16; t++) ssum += red[tid * 17 + t];
            lrow[tid] = lrow[tid] * red[tid * 17 + 16] + ssum;
        }

        #pragma unroll
        for (int i = 0; i < 8; i++) {
            float a = red[(q0 + i) * 17 + 16];
            #pragma unroll
            for (int j = 0; j < 4; j++) Oacc[i][j] *= a;
        }
        for (int k = 0; k < 64; k++) {
            float4 vv = *(const float4*)(Vs + k * ASTR_K + k0);
            float vr[4] = {vv.x, vv.y, vv.z, vv.w};
            #pragma unroll
            for (int i = 0; i < 8; i++) {
                float p = Ps[(q0 + i) * ASTR_K + k];
                #pragma unroll
                for (int j = 0; j < 4; j++)
                    Oacc[i][j] = fmaf(p, vr[j], Oacc[i][j]);
            }
        }
    }
    __syncthreads();

    #pragma unroll
    for (int i = 0; i < 8; i++) {
        float inv = 1.0f / lrow[q0 + i];
        float4 o = make_float4(Oacc[i][0] * inv, Oacc[i][1] * inv,
                               Oacc[i][2] * inv, Oacc[i][3] * inv);
        *(float4*)(out + (size_t)(b * SS + qt * 128 + q0 + i) * DD + h * 64 + k0) = o;
    }
}

// ---------------- fused residual add + LayerNorm --------------------------
__global__ __launch_bounds__(256)
void add_ln_kernel(const float* __restrict__ x, const float* __restrict__ a,
                   const float* __restrict__ g, const float* __restrict__ bb,
                   float* __restrict__ out)
{
    const int row = blockIdx.x;
    const int tid = threadIdx.x;
    __shared__ float red[256];

    const size_t off = (size_t)row * DD;
    float v[3];
    float s = 0.0f;
    #pragma unroll
    for (int i = 0; i < 3; i++) {
        int c = tid + 256 * i;
        v[i] = x[off + c] + a[off + c];
        s += v[i];
    }
    red[tid] = s; __syncthreads();
    for (int st = 128; st > 0; st >>= 1) {
        if (tid < st) red[tid] += red[tid + st];
        __syncthreads();
    }
    const float mean = red[0] * (1.0f / DD);
    __syncthreads();

    float s2 = 0.0f;
    #pragma unroll
    for (int i = 0; i < 3; i++) {
        float d = v[i] - mean;
        s2 += d * d;
    }
    red[tid] = s2; __syncthreads();
    for (int st = 128; st > 0; st >>= 1) {
        if (tid < st) red[tid] += red[tid + st];
        __syncthreads();
    }
    const float inv = rsqrtf(red[0] * (1.0f / DD) + 1e-5f);

    #pragma unroll
    for (int i = 0; i < 3; i++) {
        int c = tid + 256 * i;
        out[off + c] = g[c] * (v[i] - mean) * inv + bb[c];
    }
}

// ---------------- launch ----------------
extern "C" void kernel_launch(void* const* d_in, const int* in_sizes, int n_in,
                              void* d_out, int out_size)
{
    const int*   tokens = (const int*)  d_in[0];
    const float* we     = (const float*)d_in[1];
    const float* wqkv   = (const float*)d_in[2];
    const float* bqkv   = (const float*)d_in[3];
    const float* wproj  = (const float*)d_in[4];
    const float* bproj  = (const float*)d_in[5];
    const float* g1     = (const float*)d_in[6];
    const float* b1     = (const float*)d_in[7];
    const float* wfc    = (const float*)d_in[8];
    const float* bfc    = (const float*)d_in[9];
    const float* wpr    = (const float*)d_in[10];
    const float* bpr    = (const float*)d_in[11];
    const float* g2     = (const float*)d_in[12];
    const float* b2     = (const float*)d_in[13];
    float* out = (float*)d_out;

    float *h, *qkv, *attn, *tmp, *mid;
    __nv_bfloat16 *wex, *xe;
    cudaGetSymbolAddress((void**)&h,    g_h);
    cudaGetSymbolAddress((void**)&qkv,  g_qkv);
    cudaGetSymbolAddress((void**)&attn, g_attn);
    cudaGetSymbolAddress((void**)&tmp,  g_tmp);
    cudaGetSymbolAddress((void**)&mid,  g_mid);
    cudaGetSymbolAddress((void**)&wex,  g_wexp);
    cudaGetSymbolAddress((void**)&xe,   g_xe);

    cudaFuncSetAttribute(gemm_mma, cudaFuncAttributeMaxDynamicSharedMemorySize, GEMM_SMEM);
    cudaFuncSetAttribute(attn_flash, cudaFuncAttributeMaxDynamicSharedMemorySize, ATTN_DSMEM);

    // expand all weights (transposed, split-bf16)
    for (int l = 0; l < LL; l++) {
        __nv_bfloat16* wl = wex + (size_t)l * WL_ELEMS;
        wexpand<<<dim3(3*DD/32, DD/32), 256>>>(wqkv  + (size_t)l*DD*3*DD, wl + OFF_Q, DD, 3*DD);
        wexpand<<<dim3(DD/32,   DD/32), 256>>>(wproj + (size_t)l*DD*DD,   wl + OFF_P, DD, DD);
        wexpand<<<dim3(DF/32,   DD/32), 256>>>(wfc   + (size_t)l*DD*DF,   wl + OFF_F, DD, DF);
        wexpand<<<dim3(DD/32,   DF/32), 256>>>(wpr   + (size_t)l*DF*DD,   wl + OFF_R, DF, DD);
    }

    embed_kernel<<<MTOK, 256>>>(tokens, we, h);

    for (int l = 0; l < LL; l++) {
        const __nv_bfloat16* wl = wex + (size_t)l * WL_ELEMS;
        const float* bq = bqkv  + (size_t)l * 3 * DD;
        const float* bp = bproj + (size_t)l * DD;
        const float* gA = g1 + (size_t)l * DD;
        const float* bA = b1 + (size_t)l * DD;
        const float* bf = bfc + (size_t)l * DF;
        const float* br = bpr + (size_t)l * DD;
        const float* gB = g2 + (size_t)l * DD;
        const float* bB = b2 + (size_t)l * DD;

        act_expand<<<dim3(3, MTOK), 256>>>(h, xe, DD);
        gemm_mma<<<dim3(3*DD/128, MTOK/128), 256, GEMM_SMEM>>>(
            xe, wl + OFF_Q, bq, qkv, 3*DD, K3_D, 0);

        attn_flash<<<dim3(4, HH, BB), 256, ATTN_DSMEM>>>(qkv, attn);

        act_expand<<<dim3(3, MTOK), 256>>>(attn, xe, DD);
        gemm_mma<<<dim3(DD/128, MTOK/128), 256, GEMM_SMEM>>>(
            xe, wl + OFF_P, bp, tmp, DD, K3_D, 0);

        add_ln_kernel<<<MTOK, 256>>>(h, tmp, gA, bA, h);

        act_expand<<<dim3(3, MTOK), 256>>>(h, xe, DD);
        gemm_mma<<<dim3(DF/128, MTOK/128), 256, GEMM_SMEM>>>(
            xe, wl + OFF_F, bf, mid, DF, K3_D, 1);

        act_expand<<<dim3(12, MTOK), 256>>>(mid, xe, DF);
        gemm_mma<<<dim3(DD/128, MTOK/128), 256, GEMM_SMEM>>>(
            xe, wl + OFF_R, br, tmp, DD, K3_F, 0);

        float* o = (l == LL - 1) ? out : h;
        add_ln_kernel<<<MTOK, 256>>>(h, tmp, gB, bB, o);
    }
}

// round 7
// speedup vs baseline: 4.3170x; 1.1273x over previous
#include <cuda_runtime.h>
#include <cuda_bf16.h>
#include <math.h>
#include <stdint.h>

#define BB 8
#define SS 512
#define DD 768
#define HH 12
#define LL 12
#define DH 64
#define DF 3072
#define VV 40478
#define MTOK (BB*SS)

#define K3_D  (3*DD)       // 2304
#define K3_F  (3*DF)       // 9216

#define WQ_ELEMS ((size_t)(3*DD) * K3_D)
#define WP_ELEMS ((size_t)DD * K3_D)
#define WF_ELEMS ((size_t)DF * K3_D)
#define WR_ELEMS ((size_t)DD * K3_F)
#define WL_ELEMS (WQ_ELEMS + WP_ELEMS + WF_ELEMS + WR_ELEMS)
#define OFF_Q 0
#define OFF_P (WQ_ELEMS)
#define OFF_F (WQ_ELEMS + WP_ELEMS)
#define OFF_R (WQ_ELEMS + WP_ELEMS + WF_ELEMS)

// ---------------- static scratch ----------------
__device__ __align__(1024) float g_h[MTOK * DD];
__device__ __align__(1024) float g_qkv[MTOK * 3 * DD];
__device__ __align__(1024) float g_attn[MTOK * DD];
__device__ __align__(1024) float g_tmp[MTOK * DD];
__device__ __align__(1024) float g_mid[MTOK * DF];
__device__ __align__(1024) __nv_bfloat16 g_wexp[12 * WL_ELEMS];

// ---------------- PTX helpers (generic sm_80+ only) ----------------
__device__ __forceinline__ uint32_t smem_u32(const void* p) {
    uint32_t a;
    asm("{ .reg .u64 t; cvta.to.shared.u64 t, %1; cvt.u32.u64 %0, t; }"
        : "=r"(a) : "l"(p));
    return a;
}
__device__ __forceinline__ void cp16(uint32_t dst, const void* src) {
    asm volatile("cp.async.cg.shared.global [%0], [%1], 16;" :: "r"(dst), "l"(src));
}
__device__ __forceinline__ void cp_commit() {
    asm volatile("cp.async.commit_group;" ::);
}
template<int N>
__device__ __forceinline__ void cp_wait() {
    asm volatile("cp.async.wait_group %0;" :: "n"(N));
}
__device__ __forceinline__ void mma16816(float* c, const uint32_t* a, const uint32_t* b) {
    asm volatile(
        "mma.sync.aligned.m16n8k16.row.col.f32.bf16.bf16.f32 "
        "{%0,%1,%2,%3}, {%4,%5,%6,%7}, {%8,%9}, {%0,%1,%2,%3};"
        : "+f"(c[0]), "+f"(c[1]), "+f"(c[2]), "+f"(c[3])
        : "r"(a[0]), "r"(a[1]), "r"(a[2]), "r"(a[3]), "r"(b[0]), "r"(b[1]));
}
__device__ __forceinline__ void ldm_x4(uint32_t* r, uint32_t addr) {
    asm volatile("ldmatrix.sync.aligned.m8n8.x4.shared.b16 {%0,%1,%2,%3}, [%4];"
                 : "=r"(r[0]), "=r"(r[1]), "=r"(r[2]), "=r"(r[3]) : "r"(addr));
}

__device__ __forceinline__ float gelu_f(float x) {
    const float c = 0.7978845608028654f;
    float x3 = x * x * x;
    return 0.5f * x * (1.0f + tanhf(c * (x + 0.044715f * x3)));
}

// ---------------- embedding ----------------
__global__ void embed_kernel(const int* __restrict__ tokens,
                             const float* __restrict__ we,
                             float* __restrict__ h)
{
    int t = blockIdx.x;
    int s = t % SS;
    int tok = tokens[t];
    const float* wrow = we + (size_t)tok * DD;
    const float* prow = we + (size_t)(VV + s) * DD;
    float* hrow = h + (size_t)t * DD;
    for (int i = threadIdx.x; i < DD; i += blockDim.x)
        hrow[i] = wrow[i] + prow[i];
}

// --------- weight transpose + split: W[K,N] -> We[N,3K] = [hi|hi|lo] --------
__global__ __launch_bounds__(256)
void wexpand(const float* __restrict__ W, __nv_bfloat16* __restrict__ We,
             int K, int N)
{
    __shared__ float t[32][33];
    const int n0 = blockIdx.x * 32;
    const int k0 = blockIdx.y * 32;
    const int tx = threadIdx.x & 31;
    const int ty = threadIdx.x >> 5;
    for (int r = ty; r < 32; r += 8)
        t[r][tx] = W[(size_t)(k0 + r) * N + n0 + tx];
    __syncthreads();
    for (int r = ty; r < 32; r += 8) {
        int n = n0 + r, k = k0 + tx;
        float v = t[tx][r];
        __nv_bfloat16 hi = __float2bfloat16(v);
        float lo = v - __bfloat162float(hi);
        size_t ro = (size_t)n * (3 * K);
        We[ro + k]         = hi;
        We[ro + K + k]     = hi;
        We[ro + 2 * K + k] = __float2bfloat16(lo);
    }
}

// ---------------- fused split-bf16 mma GEMM --------------------------------
// C[M,N] = X[M,K](fp32, split on the fly to [hi|lo|hi]) @ B[N,3K]^T + bias.
// 128x128 tile, K3-chunks of 32, 4-stage pipeline (A: LDG+convert+STS 1 iter
// ahead; B: cp.async 3 ahead), 8 warps (4M x 2N), ldmatrix fragment loads.
#define MSTAGES 4
#define APAD 40
#define ASTG (128 * APAD)              // elems per tile region = 5120
#define STG_ELEMS (2 * ASTG)
#define GEMM_SMEM (MSTAGES * STG_ELEMS * 2)   // 81920 bytes

__global__ __launch_bounds__(256, 2)
void gemm_mma(const float* __restrict__ A, const __nv_bfloat16* __restrict__ B,
              const float* __restrict__ bias, float* __restrict__ C,
              int N, int K, int act)
{
    extern __shared__ __nv_bfloat16 sh[];
    const int tid  = threadIdx.x;
    const int wid  = tid >> 5;
    const int lane = tid & 31;
    const int m0 = blockIdx.y * 128;
    const int n0 = blockIdx.x * 128;
    const int wm = (wid & 3) * 32;
    const int wn = (wid >> 2) * 64;
    const int K3 = 3 * K;
    const int nk = K3 >> 5;

    const float* Af = A + (size_t)m0 * K;
    const __nv_bfloat16* Bb = B + (size_t)n0 * K3;

    // B cp.async slots: 2 x 16B per thread per stage (8KB tile)
    const int id0 = tid * 2, id1 = tid * 2 + 1;
    const int rb0 = id0 >> 2, cb0 = (id0 & 3) * 8;
    const int rb1 = id1 >> 2, cb1 = (id1 & 3) * 8;

    auto issueB = [&](int kc) {
        __nv_bfloat16* Sb = sh + (kc & 3) * STG_ELEMS + ASTG;
        const __nv_bfloat16* gb = Bb + (size_t)kc * 32;
        cp16(smem_u32(Sb + rb0 * APAD + cb0), gb + (size_t)rb0 * K3 + cb0);
        cp16(smem_u32(Sb + rb1 * APAD + cb1), gb + (size_t)rb1 * K3 + cb1);
        cp_commit();
    };

    // A slots: 4 x float4 per thread (128x32 fp32 tile)
    int rA[4], cA[4];
    #pragma unroll
    for (int i = 0; i < 4; i++) {
        int idx = tid + i * 256;
        rA[i] = idx >> 3; cA[i] = (idx & 7) * 4;
    }
    float4 pa[4];
    auto ldA = [&](int kc) {
        const int col0 = (kc * 32) % K;
        #pragma unroll
        for (int i = 0; i < 4; i++)
            pa[i] = *(const float4*)(Af + (size_t)rA[i] * K + col0 + cA[i]);
    };
    auto stsA = [&](int kc) {
        const int seg = (kc * 32) / K;     // 0:hi 1:lo 2:hi
        __nv_bfloat16* Sa = sh + (kc & 3) * STG_ELEMS;
        #pragma unroll
        for (int i = 0; i < 4; i++) {
            float4 v = pa[i];
            if (seg == 1) {
                v.x -= __bfloat162float(__float2bfloat16(v.x));
                v.y -= __bfloat162float(__float2bfloat16(v.y));
                v.z -= __bfloat162float(__float2bfloat16(v.z));
                v.w -= __bfloat162float(__float2bfloat16(v.w));
            }
            __nv_bfloat162 h0 = __floats2bfloat162_rn(v.x, v.y);
            __nv_bfloat162 h1 = __floats2bfloat162_rn(v.z, v.w);
            uint2 w;
            w.x = *reinterpret_cast<uint32_t*>(&h0);
            w.y = *reinterpret_cast<uint32_t*>(&h1);
            *reinterpret_cast<uint2*>(Sa + rA[i] * APAD + cA[i]) = w;
        }
    };

    float acc[2][8][4];
    #pragma unroll
    for (int mt = 0; mt < 2; mt++)
        #pragma unroll
        for (int nt = 0; nt < 8; nt++)
            #pragma unroll
            for (int i = 0; i < 4; i++) acc[mt][nt][i] = 0.0f;

    // prologue
    issueB(0); issueB(1); issueB(2);
    ldA(0); stsA(0);
    ldA(1);
    cp_wait<2>();
    __syncthreads();

    for (int kc = 0; kc < nk; kc++) {
        if (kc + 1 < nk) stsA(kc + 1);
        if (kc + 2 < nk) ldA(kc + 2);
        if (kc + 3 < nk) issueB(kc + 3);

        const __nv_bfloat16* Sa = sh + (kc & 3) * STG_ELEMS;
        const __nv_bfloat16* Sb = Sa + ASTG;
        #pragma unroll
        for (int ks = 0; ks < 2; ks++) {
            const int kb = ks * 16;
            uint32_t af[2][4], bfr[8][2];
            #pragma unroll
            for (int mt = 0; mt < 2; mt++) {
                int row = wm + mt * 16 + (lane & 7) + ((lane >> 3) & 1) * 8;
                int col = kb + (lane >> 4) * 8;
                ldm_x4(af[mt], smem_u32(Sa + row * APAD + col));
            }
            #pragma unroll
            for (int np = 0; np < 4; np++) {
                int nt0 = np * 2;
                int row = wn + (nt0 + (lane >> 4)) * 8 + (lane & 7);
                int col = kb + ((lane >> 3) & 1) * 8;
                uint32_t r4[4];
                ldm_x4(r4, smem_u32(Sb + row * APAD + col));
                bfr[nt0][0] = r4[0]; bfr[nt0][1] = r4[1];
                bfr[nt0 + 1][0] = r4[2]; bfr[nt0 + 1][1] = r4[3];
            }
            #pragma unroll
            for (int mt = 0; mt < 2; mt++)
                #pragma unroll
                for (int nt = 0; nt < 8; nt++)
                    mma16816(acc[mt][nt], af[mt], bfr[nt]);
        }
        if (kc + 1 < nk) { cp_wait<2>(); __syncthreads(); }
    }

    // epilogue
    #pragma unroll
    for (int mt = 0; mt < 2; mt++) {
        const int r = m0 + wm + mt * 16 + (lane >> 2);
        #pragma unroll
        for (int nt = 0; nt < 8; nt++) {
            const int c = n0 + wn + nt * 8 + (lane & 3) * 2;
            const float b0 = bias[c], b1 = bias[c + 1];
            float v0 = acc[mt][nt][0] + b0;
            float v1 = acc[mt][nt][1] + b1;
            float v2 = acc[mt][nt][2] + b0;
            float v3 = acc[mt][nt][3] + b1;
            if (act) { v0 = gelu_f(v0); v1 = gelu_f(v1); v2 = gelu_f(v2); v3 = gelu_f(v3); }
            *(float2*)(C + (size_t)r * N + c)       = make_float2(v0, v1);
            *(float2*)(C + (size_t)(r + 8) * N + c) = make_float2(v2, v3);
        }
    }
}

// ---------------- flash attention (SIMT fp32) -----------------------------
#define ASTR_Q 132
#define ASTR_K 68
#define ATTN_FLOATS (64*ASTR_Q + 64*ASTR_K + 64*ASTR_K + 128*ASTR_K + 128 + 128 + 128*17)
#define ATTN_DSMEM (ATTN_FLOATS * 4)

__global__ __launch_bounds__(256)
void attn_flash(const float* __restrict__ qkv, float* __restrict__ out)
{
    extern __shared__ float af[];
    float* Qs   = af;
    float* Ks   = Qs + 64 * ASTR_Q;
    float* Vs   = Ks + 64 * ASTR_K;
    float* Ps   = Vs + 64 * ASTR_K;
    float* mrow = Ps + 128 * ASTR_K;
    float* lrow = mrow + 128;
    float* red  = lrow + 128;

    const int tid = threadIdx.x;
    const int tx = tid & 15;
    const int ty = tid >> 4;
    const int q0 = ty * 8;
    const int k0 = tx * 4;
    const int qt = blockIdx.x;
    const int h  = blockIdx.y;
    const int b  = blockIdx.z;
    const float* base = qkv + (size_t)b * SS * (3 * DD);

    for (int i = tid; i < 128 * 16; i += 256) {
        int q = i >> 4, d = (i & 15) * 4;
        float4 v = *(const float4*)(base + (size_t)(qt * 128 + q) * (3 * DD) + h * 64 + d);
        Qs[(d + 0) * ASTR_Q + q] = v.x * 0.125f;
        Qs[(d + 1) * ASTR_Q + q] = v.y * 0.125f;
        Qs[(d + 2) * ASTR_Q + q] = v.z * 0.125f;
        Qs[(d + 3) * ASTR_Q + q] = v.w * 0.125f;
    }
    if (tid < 128) { mrow[tid] = -1e30f; lrow[tid] = 0.0f; }

    float Oacc[8][4];
    #pragma unroll
    for (int i = 0; i < 8; i++)
        #pragma unroll
        for (int j = 0; j < 4; j++) Oacc[i][j] = 0.0f;

    const int nkt = (qt + 1) * 2;
    for (int kt = 0; kt < nkt; kt++) {
        __syncthreads();
        for (int i = tid; i < 64 * 16; i += 256) {
            int kk = i >> 4, d = (i & 15) * 4;
            const float* kp = base + (size_t)(kt * 64 + kk) * (3 * DD) + DD + h * 64 + d;
            float4 v = *(const float4*)kp;
            Ks[(d + 0) * ASTR_K + kk] = v.x;
            Ks[(d + 1) * ASTR_K + kk] = v.y;
            Ks[(d + 2) * ASTR_K + kk] = v.z;
            Ks[(d + 3) * ASTR_K + kk] = v.w;
            const float* vp = base + (size_t)(kt * 64 + kk) * (3 * DD) + 2 * DD + h * 64 + d;
            *(float4*)(Vs + kk * ASTR_K + d) = *(const float4*)vp;
        }
        __syncthreads();

        float s[8][4];
        #pragma unroll
        for (int i = 0; i < 8; i++)
            #pragma unroll
            for (int j = 0; j < 4; j++) s[i][j] = 0.0f;

        for (int d = 0; d < 64; d++) {
            float4 kv = *(const float4*)(Ks + d * ASTR_K + k0);
            float4 qa = *(const float4*)(Qs + d * ASTR_Q + q0);
            float4 qb = *(const float4*)(Qs + d * ASTR_Q + q0 + 4);
            float qv[8] = {qa.x, qa.y, qa.z, qa.w, qb.x, qb.y, qb.z, qb.w};
            float kk[4] = {kv.x, kv.y, kv.z, kv.w};
            #pragma unroll
            for (int i = 0; i < 8; i++)
                #pragma unroll
                for (int j = 0; j < 4; j++)
                    s[i][j] = fmaf(qv[i], kk[j], s[i][j]);
        }

        if (kt >= 2 * qt) {
            const int diag = (kt - 2 * qt) * 64;
            #pragma unroll
            for (int i = 0; i < 8; i++)
                #pragma unroll
                for (int j = 0; j < 4; j++)
                    if (q0 + i < diag + k0 + j) s[i][j] = -1e9f;
        }

        #pragma unroll
        for (int i = 0; i < 8; i++) {
            float m4 = fmaxf(fmaxf(s[i][0], s[i][1]), fmaxf(s[i][2], s[i][3]));
            red[(q0 + i) * 17 + tx] = m4;
        }
        __syncthreads();
        if (tid < 128) {
            float m = mrow[tid];
            float mn = m;
            #pragma unroll
            for (int t = 0; t < 16; t++) mn = fmaxf(mn, red[tid * 17 + t]);
            red[tid * 17 + 16] = __expf(m - mn);
            mrow[tid] = mn;
        }
        __syncthreads();

        #pragma unroll
        for (int i = 0; i < 8; i++) {
            float m = mrow[q0 + i];
            float ps = 0.0f;
            #pragma unroll
            for (int j = 0; j < 4; j++) {
                float p = __expf(s[i][j] - m);
                Ps[(q0 + i) * ASTR_K + k0 + j] = p;
                ps += p;
            }
            red[(q0 + i) * 17 + tx] = ps;
        }
        __syncthreads();
        if (tid < 128) {
            float ssum = 0.0f;
            #pragma unroll
            for (int t = 0; t < 16; t++) ssum += red[tid * 17 + t];
            lrow[tid] = lrow[tid] * red[tid * 17 + 16] + ssum;
        }

        #pragma unroll
        for (int i = 0; i < 8; i++) {
            float a = red[(q0 + i) * 17 + 16];
            #pragma unroll
            for (int j = 0; j < 4; j++) Oacc[i][j] *= a;
        }
        for (int k = 0; k < 64; k++) {
            float4 vv = *(const float4*)(Vs + k * ASTR_K + k0);
            float vr[4] = {vv.x, vv.y, vv.z, vv.w};
            #pragma unroll
            for (int i = 0; i < 8; i++) {
                float p = Ps[(q0 + i) * ASTR_K + k];
                #pragma unroll
                for (int j = 0; j < 4; j++)
                    Oacc[i][j] = fmaf(p, vr[j], Oacc[i][j]);
            }
        }
    }
    __syncthreads();

    #pragma unroll
    for (int i = 0; i < 8; i++) {
        float inv = 1.0f / lrow[q0 + i];
        float4 o = make_float4(Oacc[i][0] * inv, Oacc[i][1] * inv,
                               Oacc[i][2] * inv, Oacc[i][3] * inv);
        *(float4*)(out + (size_t)(b * SS + qt * 128 + q0 + i) * DD + h * 64 + k0) = o;
    }
}

// ---------------- fused residual add + LayerNorm --------------------------
__global__ __launch_bounds__(256)
void add_ln_kernel(const float* __restrict__ x, const float* __restrict__ a,
                   const float* __restrict__ g, const float* __restrict__ bb,
                   float* __restrict__ out)
{
    const int row = blockIdx.x;
    const int tid = threadIdx.x;
    __shared__ float red[256];

    const size_t off = (size_t)row * DD;
    float v[3];
    float s = 0.0f;
    #pragma unroll
    for (int i = 0; i < 3; i++) {
        int c = tid + 256 * i;
        v[i] = x[off + c] + a[off + c];
        s += v[i];
    }
    red[tid] = s; __syncthreads();
    for (int st = 128; st > 0; st >>= 1) {
        if (tid < st) red[tid] += red[tid + st];
        __syncthreads();
    }
    const float mean = red[0] * (1.0f / DD);
    __syncthreads();

    float s2 = 0.0f;
    #pragma unroll
    for (int i = 0; i < 3; i++) {
        float d = v[i] - mean;
        s2 += d * d;
    }
    red[tid] = s2; __syncthreads();
    for (int st = 128; st > 0; st >>= 1) {
        if (tid < st) red[tid] += red[tid + st];
        __syncthreads();
    }
    const float inv = rsqrtf(red[0] * (1.0f / DD) + 1e-5f);

    #pragma unroll
    for (int i = 0; i < 3; i++) {
        int c = tid + 256 * i;
        out[off + c] = g[c] * (v[i] - mean) * inv + bb[c];
    }
}

// ---------------- launch ----------------
extern "C" void kernel_launch(void* const* d_in, const int* in_sizes, int n_in,
                              void* d_out, int out_size)
{
    const int*   tokens = (const int*)  d_in[0];
    const float* we     = (const float*)d_in[1];
    const float* wqkv   = (const float*)d_in[2];
    const float* bqkv   = (const float*)d_in[3];
    const float* wproj  = (const float*)d_in[4];
    const float* bproj  = (const float*)d_in[5];
    const float* g1     = (const float*)d_in[6];
    const float* b1     = (const float*)d_in[7];
    const float* wfc    = (const float*)d_in[8];
    const float* bfc    = (const float*)d_in[9];
    const float* wpr    = (const float*)d_in[10];
    const float* bpr    = (const float*)d_in[11];
    const float* g2     = (const float*)d_in[12];
    const float* b2     = (const float*)d_in[13];
    float* out = (float*)d_out;

    float *h, *qkv, *attn, *tmp, *mid;
    __nv_bfloat16 *wex;
    cudaGetSymbolAddress((void**)&h,    g_h);
    cudaGetSymbolAddress((void**)&qkv,  g_qkv);
    cudaGetSymbolAddress((void**)&attn, g_attn);
    cudaGetSymbolAddress((void**)&tmp,  g_tmp);
    cudaGetSymbolAddress((void**)&mid,  g_mid);
    cudaGetSymbolAddress((void**)&wex,  g_wexp);

    cudaFuncSetAttribute(gemm_mma, cudaFuncAttributeMaxDynamicSharedMemorySize, GEMM_SMEM);
    cudaFuncSetAttribute(attn_flash, cudaFuncAttributeMaxDynamicSharedMemorySize, ATTN_DSMEM);

    // expand all weights (transposed, split-bf16)
    for (int l = 0; l < LL; l++) {
        __nv_bfloat16* wl = wex + (size_t)l * WL_ELEMS;
        wexpand<<<dim3(3*DD/32, DD/32), 256>>>(wqkv  + (size_t)l*DD*3*DD, wl + OFF_Q, DD, 3*DD);
        wexpand<<<dim3(DD/32,   DD/32), 256>>>(wproj + (size_t)l*DD*DD,   wl + OFF_P, DD, DD);
        wexpand<<<dim3(DF/32,   DD/32), 256>>>(wfc   + (size_t)l*DD*DF,   wl + OFF_F, DD, DF);
        wexpand<<<dim3(DD/32,   DF/32), 256>>>(wpr   + (size_t)l*DF*DD,   wl + OFF_R, DF, DD);
    }

    embed_kernel<<<MTOK, 256>>>(tokens, we, h);

    for (int l = 0; l < LL; l++) {
        const __nv_bfloat16* wl = wex + (size_t)l * WL_ELEMS;
        const float* bq = bqkv  + (size_t)l * 3 * DD;
        const float* bp = bproj + (size_t)l * DD;
        const float* gA = g1 + (size_t)l * DD;
        const float* bA = b1 + (size_t)l * DD;
        const float* bf = bfc + (size_t)l * DF;
        const float* br = bpr + (size_t)l * DD;
        const float* gB = g2 + (size_t)l * DD;
        const float* bB = b2 + (size_t)l * DD;

        gemm_mma<<<dim3(3*DD/128, MTOK/128), 256, GEMM_SMEM>>>(
            h, wl + OFF_Q, bq, qkv, 3*DD, DD, 0);

        attn_flash<<<dim3(4, HH, BB), 256, ATTN_DSMEM>>>(qkv, attn);

        gemm_mma<<<dim3(DD/128, MTOK/128), 256, GEMM_SMEM>>>(
            attn, wl + OFF_P, bp, tmp, DD, DD, 0);

        add_ln_kernel<<<MTOK, 256>>>(h, tmp, gA, bA, h);

        gemm_mma<<<dim3(DF/128, MTOK/128), 256, GEMM_SMEM>>>(
            h, wl + OFF_F, bf, mid, DF, DD, 1);

        gemm_mma<<<dim3(DD/128, MTOK/128), 256, GEMM_SMEM>>>(
            mid, wl + OFF_R, br, tmp, DD, DF, 0);

        float* o = (l == LL - 1) ? out : h;
        add_ln_kernel<<<MTOK, 256>>>(h, tmp, gB, bB, o);
    }
}